// round 12
// baseline (speedup 1.0000x reference)
#include <cuda_runtime.h>

#define CLASSES 21
#define TPB 128           // threads per block
#define HALF 64           // anchors per block (2 threads per anchor)
#define TMAXS 256         // max targets held in SMEM (actual T = 200)
#define MAXBLK 8192       // max grid size for partial arrays

// 3 * 2^22 : quantizer scale so that  g = inter/S >= 1/3  <=>  iq >= 2^22
#define INV_C (1.0f / 12582912.0f)

// ---------------- per-block partials + completion ticket ---------------------
__device__ double   g_part_cls[MAXBLK];
__device__ double   g_part_reg[MAXBLK];
__device__ int      g_part_pos[MAXBLK];
__device__ unsigned g_ticket;   // zero-init; reset by finalizing block

// smooth L1
__device__ __forceinline__ float sl1(float d) {
    float ad = fabsf(d);
    return (ad < 1.0f) ? 0.5f * ad * ad : ad - 0.5f;
}

// negative-form focal term: p(x)^2 * softplus(x)
__device__ __forceinline__ float neg_focal(float x) {
    float ax = fabsf(x);
    float e  = __expf(-ax);
    float dd = 1.0f + e;
    float r  = __fdividef(1.0f, dd);
    float p  = (x >= 0.0f) ? r : e * r;          // sigmoid(x), stable
    float spx = fmaxf(x, 0.0f) + __logf(dd);     // softplus(x), stable
    return p * p * spx;
}

// correction for the single target=1 class: 0.25*pos_term - 0.75*neg_term
__device__ __forceinline__ float pos_corr(float xl) {
    float ax = fabsf(xl);
    float e  = __expf(-ax);
    float dd = 1.0f + e;
    float r  = __fdividef(1.0f, dd);
    float p  = (xl >= 0.0f) ? r : e * r;         // sigmoid
    float pm = (xl >= 0.0f) ? e * r : r;         // 1 - sigmoid, stable
    float spx  = fmaxf(xl, 0.0f) + __logf(dd);   // softplus(x)
    float spnx = spx - xl;                       // softplus(-x)
    return 0.25f * pm * pm * spnx - 0.75f * p * p * spx;
}

__global__ __launch_bounds__(TPB, 12) void rn_loss(
    const float*  __restrict__ cls,
    const float4* __restrict__ box,
    const float4* __restrict__ anc,
    const float4* __restrict__ tb,
    const int*    __restrict__ tl,
    float* __restrict__ out, int nout,
    int A, int T)
{
    __shared__ float4   s_tb[TMAXS];
    __shared__ float    s_areaC[TMAXS];          // target area * INV_C
    __shared__ int      s_tl[TMAXS];
    __shared__ unsigned s_key[TPB];              // per-thread partial keys
    __shared__ float    s_cls[HALF * CLASSES];   // staged logits (64 anchors)
    __shared__ float    s_wc[TPB / 32];
    __shared__ float    s_wr[TPB / 32];
    __shared__ int      s_wp[TPB / 32];
    __shared__ double   s_dc[TPB / 32];
    __shared__ double   s_dr[TPB / 32];
    __shared__ int      s_dp[TPB / 32];
    __shared__ bool     s_last;

    const int tid  = threadIdx.x;
    const int lane = tid & 31;
    const int wrp  = tid >> 5;
    const int i    = tid & (HALF - 1);   // anchor slot within block
    const int h    = tid >> 6;           // target-half: 0 or 1

    for (int t = tid; t < T; t += TPB) {
        float4 b   = tb[t];
        s_tb[t]    = b;
        s_areaC[t] = ((b.z - b.x) * (b.w - b.y)) * INV_C;
        s_tl[t]    = tl[t];
    }
    __syncthreads();

    // ---- 2 threads per anchor: halves of the target range ----
    const int  a     = blockIdx.x * HALF + i;
    const bool valid = a < A;
    float4 an     = valid ? anc[a] : make_float4(2.f, 2.f, 2.001f, 2.001f);
    float  areaBC = ((an.z - an.x) * (an.w - an.y)) * INV_C;

    const int Tm = (T + 1) >> 1;
    const int t0 = h ? Tm : 0;
    const int t1 = h ? T  : Tm;

    unsigned best = 0u;
#pragma unroll 4
    for (int t = t0; t < t1; t++) {
        float4 b  = s_tb[t];
        float lx = fmaxf(b.x, an.x), ly = fmaxf(b.y, an.y);
        float rx = fminf(b.z, an.z), ry = fminf(b.w, an.w);
        float w  = fmaxf(rx - lx, 0.f), hh = fmaxf(ry - ly, 0.f);
        float inter = w * hh;
        float Sp = s_areaC[t] + areaBC;        // (area_t + area_a) * INV_C
        float gq = __fdividef(inter, Sp);      // g * 3*2^22,  g = inter/S
        unsigned iq = __float2uint_rz(gq);
        best = umax(best, iq * 256u + (unsigned)t);
    }
    s_key[tid] = best;

    // ---- stage this block's logits (64 anchors x 21), fully coalesced ----
    {
        const long long base  = (long long)blockIdx.x * HALF * CLASSES;
        const long long limit = (long long)A * CLASSES;
        for (int j = tid; j < HALF * CLASSES; j += TPB) {
            long long gi = base + j;
            s_cls[j] = (gi < limit) ? __ldg(cls + gi) : 0.0f;
        }
    }
    __syncthreads();

    // ---- merge the two halves' keys ----
    const unsigned mkey = umax(s_key[i], s_key[i + HALF]);
    const int  bt  = (int)(mkey & 255u);
    const bool pos = (mkey >> 8) >= (1u << 22);   // iou >= 0.5
    const int  lbl = pos ? s_tl[bt] : 0;          // background -> class 0

    // ---- focal (split classes between halves) + regression (half 0) ----
    float cls_acc = 0.f, reg_acc = 0.f;
    int   pos_acc = 0;
    if (valid) {
        const float* me = s_cls + i * CLASSES;    // stride-21: conflict-free

        float fsum = 0.0f;
        if (h == 0) {
#pragma unroll
            for (int c = 0; c < 11; c++) fsum += neg_focal(me[c]);
        } else {
#pragma unroll
            for (int c = 11; c < CLASSES; c++) fsum += neg_focal(me[c]);
        }
        cls_acc = 0.75f * fsum;
        // the half owning the label adds the target-class correction
        if ((h == 0) == (lbl < 11)) cls_acc += pos_corr(me[lbl]);

        if (h == 0 && pos) {
            float4 bp  = box[a];
            float4 tbv = s_tb[bt];
            float acx = 0.5f * (an.x + an.z), acy = 0.5f * (an.y + an.w);
            float aw  = an.z - an.x,          ah  = an.w - an.y;
            float iaw = __fdividef(1.0f, aw), iah = __fdividef(1.0f, ah);

            float pcx = 0.5f * (bp.x + bp.z), pcy = 0.5f * (bp.y + bp.w);
            float pw  = bp.z - bp.x,          ph  = bp.w - bp.y;
            float tcx = 0.5f * (tbv.x + tbv.z), tcy = 0.5f * (tbv.y + tbv.w);
            float tw  = tbv.z - tbv.x,          th  = tbv.w - tbv.y;

            float d0 = (pcx - acx) * iaw - (tcx - acx) * iaw;
            float d1 = (pcy - acy) * iah - (tcy - acy) * iah;
            float d2 = __logf(pw * iaw) - __logf(tw * iaw);
            float d3 = __logf(ph * iah) - __logf(th * iah);

            reg_acc = sl1(d0) + sl1(d1) + sl1(d2) + sl1(d3);
            pos_acc = 1;
        }
    }

    // ---- block reduction: warp shuffle then cross-warp ----
#pragma unroll
    for (int s = 16; s > 0; s >>= 1) {
        cls_acc += __shfl_down_sync(0xffffffffu, cls_acc, s);
        reg_acc += __shfl_down_sync(0xffffffffu, reg_acc, s);
        pos_acc += __shfl_down_sync(0xffffffffu, pos_acc, s);
    }
    if (lane == 0) { s_wc[wrp] = cls_acc; s_wr[wrp] = reg_acc; s_wp[wrp] = pos_acc; }
    __syncthreads();

    if (tid == 0) {
        double c = 0.0, r = 0.0; int p = 0;
#pragma unroll
        for (int w = 0; w < TPB / 32; w++) { c += (double)s_wc[w]; r += (double)s_wr[w]; p += s_wp[w]; }
        g_part_cls[blockIdx.x] = c;
        g_part_reg[blockIdx.x] = r;
        g_part_pos[blockIdx.x] = p;
        __threadfence();
        unsigned tk = atomicAdd(&g_ticket, 1u);
        s_last = (tk == gridDim.x - 1);
    }
    __syncthreads();

    // ---- last block finalizes ----
    if (s_last) {
        __threadfence();
        double c = 0.0, r = 0.0; int p = 0;
        for (int j = tid; j < (int)gridDim.x; j += TPB) {
            c += g_part_cls[j];
            r += g_part_reg[j];
            p += g_part_pos[j];
        }
#pragma unroll
        for (int s = 16; s > 0; s >>= 1) {
            c += __shfl_down_sync(0xffffffffu, c, s);
            r += __shfl_down_sync(0xffffffffu, r, s);
            p += __shfl_down_sync(0xffffffffu, p, s);
        }
        if (lane == 0) { s_dc[wrp] = c; s_dr[wrp] = r; s_dp[wrp] = p; }
        __syncthreads();
        if (tid == 0) {
            double cc = 0.0, rr = 0.0; int pp = 0;
#pragma unroll
            for (int w = 0; w < TPB / 32; w++) { cc += s_dc[w]; rr += s_dr[w]; pp += s_dp[w]; }
            double norm = (pp < 1) ? 1.0 : (double)pp;
            float wc = (float)(cc / norm);
            float wr = (pp > 0) ? (float)(rr / (norm * 4.0)) : 0.0f;
            if (nout > 0) out[0] = wc + wr;
            if (nout > 1) out[1] = wc;
            if (nout > 2) out[2] = wr;
            g_ticket = 0;   // reset for next (graph-replayed) call
        }
    }
}

extern "C" void kernel_launch(void* const* d_in, const int* in_sizes, int n_in,
                              void* d_out, int out_size) {
    const float*  cls = (const float*)d_in[0];
    const float4* box = (const float4*)d_in[1];
    const float4* anc = (const float4*)d_in[2];
    const float4* tb  = (const float4*)d_in[3];
    const int*    tl  = (const int*)d_in[4];

    int A = in_sizes[0] / CLASSES;   // flattened anchor count
    int T = in_sizes[4];             // flattened target count
    if (T > TMAXS) T = TMAXS;

    int grid = (A + HALF - 1) / HALF;  // A=196608 -> 3072
    if (grid > MAXBLK) grid = MAXBLK;

    rn_loss<<<grid, TPB>>>(cls, box, anc, tb, tl,
                           (float*)d_out, out_size, A, T);
}